// round 12
// baseline (speedup 1.0000x reference)
#include <cuda_runtime.h>
#include <math.h>

#define TT 2048
#define BB 64
#define DD 256
#define HH 512

#define NGROUPS 8
#define GC 16         // CTAs per group
#define GB 8          // batch elems per group
#define JC 32         // output columns owned per CTA
#define NT 256        // 8 warps
#define HPAD 12       // hbuf row pad (16B-aligned rows, conflict-free LDS.128)

// ---------------- packed fp32x2 helpers ----------------
#define FMA_X2(d, a, b, c) \
    asm("fma.rn.f32x2 %0, %1, %2, %3;" : "=l"(d) : "l"(a), "l"(b), "l"(c))
#define ADD_X2(d, a, b) \
    asm("add.rn.f32x2 %0, %1, %2;" : "=l"(d) : "l"(a), "l"(b))
#define DUP_X2(d, s) \
    asm("mov.b64 %0, {%1, %1};" : "=l"(d) : "r"(__float_as_uint(s)))
#define UNPACK_X2(lo, hi, p) \
    asm("mov.b64 {%0, %1}, %2;" : "=r"(lo), "=r"(hi) : "l"(p))

// ---------------- device scratch ----------------
__device__ float g_Gx[(size_t)TT * 3 * BB * HH];
__device__ float g_h[BB * HH];
__device__ float g_rh[BB * HH];
__device__ __align__(64) unsigned g_slot[NGROUPS][16];  // per-CTA flag slots (one 64B line/group)
__device__ unsigned g_bcnt[NGROUPS];                    // init barrier only
__device__ unsigned g_bgen[NGROUPS];

// ---------------- init barrier (R5 generation barrier; replay-safe) ----------------
__device__ __forceinline__ void init_barrier(int grp) {
    __syncthreads();
    if (threadIdx.x == 0) {
        unsigned gen;
        asm volatile("ld.acquire.gpu.global.u32 %0, [%1];"
                     : "=r"(gen) : "l"(&g_bgen[grp]));
        unsigned old;
        asm volatile("atom.acq_rel.gpu.global.add.u32 %0, [%1], %2;"
                     : "=r"(old) : "l"(&g_bcnt[grp]), "r"(1u));
        if (old == GC - 1u) {
            asm volatile("st.relaxed.gpu.global.u32 [%0], %1;"
                         :: "l"(&g_bcnt[grp]), "r"(0u));
            asm volatile("st.release.gpu.global.u32 [%0], %1;"
                         :: "l"(&g_bgen[grp]), "r"(gen + 1u));
        } else {
            unsigned cur;
            do {
                asm volatile("ld.acquire.gpu.global.u32 %0, [%1];"
                             : "=r"(cur) : "l"(&g_bgen[grp]));
            } while (cur == gen);
        }
    }
    __syncthreads();
}

// ---------------- flag-slot barrier: no atomics, single hop ----------------
__device__ __forceinline__ void slot_arrive(int grp, int rank, unsigned val) {
    __syncthreads();   // all warps' work (incl. L2 stores) issued before flag
    if (threadIdx.x == 0) {
        asm volatile("st.release.gpu.global.u32 [%0], %1;"
                     :: "l"(&g_slot[grp][rank]), "r"(val));
    }
}
__device__ __forceinline__ void slot_wait(int grp, unsigned val) {
    if (threadIdx.x == 0) {
        const unsigned* base = &g_slot[grp][0];
        unsigned mn;
        do {
            unsigned a0, a1, a2, a3, b0, b1, b2, b3;
            unsigned c0, c1, c2, c3, d0, d1, d2, d3;
            asm volatile("ld.acquire.gpu.global.v4.u32 {%0,%1,%2,%3}, [%4];"
                         : "=r"(a0), "=r"(a1), "=r"(a2), "=r"(a3) : "l"(base));
            asm volatile("ld.acquire.gpu.global.v4.u32 {%0,%1,%2,%3}, [%4];"
                         : "=r"(b0), "=r"(b1), "=r"(b2), "=r"(b3) : "l"(base + 4));
            asm volatile("ld.acquire.gpu.global.v4.u32 {%0,%1,%2,%3}, [%4];"
                         : "=r"(c0), "=r"(c1), "=r"(c2), "=r"(c3) : "l"(base + 8));
            asm volatile("ld.acquire.gpu.global.v4.u32 {%0,%1,%2,%3}, [%4];"
                         : "=r"(d0), "=r"(d1), "=r"(d2), "=r"(d3) : "l"(base + 12));
            mn = min(min(min(a0, a1), min(a2, a3)), min(min(b0, b1), min(b2, b3)));
            mn = min(mn, min(min(min(c0, c1), min(c2, c3)), min(min(d0, d1), min(d2, d3))));
        } while (mn < val);
    }
    __syncthreads();
}

// =====================================================================================
// Phase 1 (R5-proven, unchanged)
// =====================================================================================
__global__ void __launch_bounds__(256) phase1_gemm(
    const float* __restrict__ x,
    const float* __restrict__ Wz, const float* __restrict__ bz,
    const float* __restrict__ Wr, const float* __restrict__ br,
    const float* __restrict__ Wh, const float* __restrict__ bh)
{
    __shared__ float xs[32 * 132];
    __shared__ float ws[32 * 64];

    const int gate = blockIdx.y >> 3;
    const int jt0  = (blockIdx.y & 7) * 64;
    const float* W    = (gate == 0) ? Wz : ((gate == 1) ? Wr : Wh);
    const float* bias = (gate == 0) ? bz : ((gate == 1) ? br : bh);
    const int m0  = blockIdx.x * 128;
    const int tid = threadIdx.x;
    const int tn = tid & 15;
    const int tm = tid >> 4;

    unsigned long long pa[4][4];
#pragma unroll
    for (int i = 0; i < 4; i++)
#pragma unroll
        for (int j = 0; j < 4; j++) pa[i][j] = 0ull;

    for (int kc = 0; kc < 8; kc++) {
#pragma unroll
        for (int i = 0; i < 16; i++) {
            int idx = tid + i * 256;
            int row = idx >> 5, kk = idx & 31;
            xs[kk * 132 + row] = x[(size_t)(m0 + row) * DD + kc * 32 + kk];
        }
#pragma unroll
        for (int i = 0; i < 8; i++) {
            int idx = tid + i * 256;
            int kk = idx >> 6, jj = idx & 63;
            ws[kk * 64 + jj] = W[(size_t)(kc * 32 + kk) * HH + jt0 + jj];
        }
        __syncthreads();
#pragma unroll 8
        for (int kk = 0; kk < 32; kk++) {
            float4 w4 = *(const float4*)&ws[kk * 64 + tn * 4];
            ulonglong2 xL = *(const ulonglong2*)&xs[kk * 132 + tm * 8];
            ulonglong2 xH = *(const ulonglong2*)&xs[kk * 132 + tm * 8 + 4];
            unsigned long long hp[4] = {xL.x, xL.y, xH.x, xH.y};
            unsigned long long wd[4];
            DUP_X2(wd[0], w4.x); DUP_X2(wd[1], w4.y);
            DUP_X2(wd[2], w4.z); DUP_X2(wd[3], w4.w);
#pragma unroll
            for (int i = 0; i < 4; i++)
#pragma unroll
                for (int j = 0; j < 4; j++)
                    FMA_X2(pa[i][j], hp[i], wd[j], pa[i][j]);
        }
        __syncthreads();
    }

#pragma unroll
    for (int i = 0; i < 4; i++) {
#pragma unroll
        for (int j = 0; j < 4; j++) {
            unsigned lo, hi;
            UNPACK_X2(lo, hi, pa[i][j]);
            float bj = bias[jt0 + tn * 4 + j];
            int mA = m0 + tm * 8 + 2 * i;
            int tA = mA >> 6, bA = mA & 63;
            g_Gx[(((size_t)tA * 3 + gate) * BB + bA) * HH + jt0 + tn * 4 + j] =
                __uint_as_float(lo) + bj;
            int mB = mA + 1;
            int tB = mB >> 6, bB = mB & 63;
            g_Gx[(((size_t)tB * 3 + gate) * BB + bB) * HH + jt0 + tn * 4 + j] =
                __uint_as_float(hi) + bj;
        }
    }
}

// =====================================================================================
// Phase 2: R5 skeleton + flag-slot barriers + next-step Gx prefetch in barrier-2 shadow.
// Warp w: stage1 gate = w>>2 (0=z,1=r), jt = w&3 (8 cols), full K=512.
//         stage2 khalf = w>>2 (K/2),    jt = w&3, smem combine.
// =====================================================================================
__global__ void __launch_bounds__(NT, 1) phase2_gru(
    const float* __restrict__ h0in,
    const float* __restrict__ Wz,
    const float* __restrict__ Wr,
    const float* __restrict__ Wh,
    float* __restrict__ out)
{
    extern __shared__ float sm[];
    float* wzs  = sm;                     // [512][32] swizzled
    float* wrs  = wzs + HH * JC;
    float* whs  = wrs + HH * JC;
    float* hbuf = whs + HH * JC;          // [512][HPAD]
    float* z_s  = hbuf + HH * HPAD;       // [8][32]
    float* ho_s = z_s + GB * JC;          // [8][32]
    unsigned long long* partU = (unsigned long long*)(ho_s + GB * JC);  // [4][32]

    const int grp  = blockIdx.x >> 4;
    const int rank = blockIdx.x & 15;
    const int b0 = grp * GB;
    const int j0 = rank * JC;
    const int tid  = threadIdx.x;
    const int warp = tid >> 5;
    const int lane = tid & 31;

    // reset own flag slot, then init barrier (publishes resets; replay-safe)
    if (tid == 0)
        asm volatile("st.relaxed.gpu.global.u32 [%0], %1;"
                     :: "l"(&g_slot[grp][rank]), "r"(0u));

    // resident recurrent weights (rows DD..DD+511), float4-slot XOR swizzle
    for (int idx = tid; idx < HH * JC; idx += NT) {
        int k = idx >> 5, jl = idx & 31;
        int phys = k * JC + ((((jl >> 2) ^ (k & 7))) << 2) + (jl & 3);
        size_t goff = (size_t)(DD + k) * HH + j0 + jl;
        wzs[phys] = Wz[goff];
        wrs[phys] = Wr[goff];
        whs[phys] = Wh[goff];
    }
    init_barrier(grp);

    const int gate1 = warp >> 2;            // stage1: 0=z, 1=r
    const int jt    = warp & 3;             // 8-col tile (both stages)
    const int khalf = warp >> 2;            // stage2 k-half
    const int slotA = (jt * 2) ^ (lane & 7);
    const int slotB = (jt * 2 + 1) ^ (lane & 7);
    const int bp    = lane >> 3;            // owned b-pair
    const int jl_o  = jt * 8 + (lane & 7);  // owned column
    const int fb    = warp;                 // fill: batch row = warp
    const int fk    = lane;                 // fill: k quad base

    // Gx prefetch for t=0
    float gx1lo, gx1hi, gx2lo = 0.f, gx2hi = 0.f;
    {
        size_t r1 = (((size_t)0 * 3 + gate1) * BB + b0 + 2 * bp) * HH + j0 + jl_o;
        gx1lo = __ldg(&g_Gx[r1]);
        gx1hi = __ldg(&g_Gx[r1 + HH]);
        if (khalf == 0) {
            size_t r2 = (((size_t)0 * 3 + 2) * BB + b0 + 2 * bp) * HH + j0 + jl_o;
            gx2lo = __ldg(&g_Gx[r2]);
            gx2hi = __ldg(&g_Gx[r2 + HH]);
        }
    }

    for (int t = 0; t < TT; t++) {
        // ---------------- fill hbuf with h (vectorized, coalesced) ----------------
        const float* hsrc = (t == 0) ? h0in : (const float*)g_h;
        {
            float4 hv[4];
#pragma unroll
            for (int o = 0; o < 4; o++)
                hv[o] = __ldcg((const float4*)&hsrc[(size_t)(b0 + fb) * HH + (o * 32 + fk) * 4]);
#pragma unroll
            for (int o = 0; o < 4; o++) {
                int k = (o * 32 + fk) * 4;
                hbuf[(k + 0) * HPAD + fb] = hv[o].x;
                hbuf[(k + 1) * HPAD + fb] = hv[o].y;
                hbuf[(k + 2) * HPAD + fb] = hv[o].z;
                hbuf[(k + 3) * HPAD + fb] = hv[o].w;
            }
        }
        __syncthreads();

        // stash h_old for own columns
        { int b = tid >> 5, jl = tid & 31; ho_s[tid] = hbuf[(j0 + jl) * HPAD + b]; }

        // ================= stage 1 dot (full K=512 per warp) =================
        unsigned long long a2[32];
#pragma unroll
        for (int v = 0; v < 32; v++) a2[v] = 0ull;
        {
            const float4* wp = (const float4*)((gate1 ? wrs : wzs) + lane * JC);
            const char*   hp = (const char*)(hbuf + lane * HPAD);
#pragma unroll
            for (int i = 0; i < 16; i++) {
                float4 w0 = wp[slotA], w1 = wp[slotB];
                ulonglong2 hL = *(const ulonglong2*)hp;
                ulonglong2 hH = *(const ulonglong2*)(hp + 16);
                unsigned long long hb[4] = {hL.x, hL.y, hH.x, hH.y};
                unsigned long long wd[8];
                DUP_X2(wd[0], w0.x); DUP_X2(wd[1], w0.y);
                DUP_X2(wd[2], w0.z); DUP_X2(wd[3], w0.w);
                DUP_X2(wd[4], w1.x); DUP_X2(wd[5], w1.y);
                DUP_X2(wd[6], w1.z); DUP_X2(wd[7], w1.w);
#pragma unroll
                for (int p = 0; p < 4; p++)
#pragma unroll
                    for (int j = 0; j < 8; j++)
                        FMA_X2(a2[p * 8 + j], hb[p], wd[j], a2[p * 8 + j]);
                wp += 32 * JC / 4;
                hp += 32 * HPAD * 4;
            }
        }
#pragma unroll
        for (int s = 0; s < 5; s++) {
            const int m = 16 >> s, half = 16 >> s;
            bool up = (lane & m) != 0;
#pragma unroll
            for (int i = 0; i < half; i++) {
                unsigned long long send = up ? a2[i] : a2[i + half];
                unsigned long long r = __shfl_xor_sync(0xffffffffu, send, m);
                unsigned long long keep = up ? a2[i + half] : a2[i];
                ADD_X2(a2[i], keep, r);
            }
        }
        {
            unsigned lo, hi;
            UNPACK_X2(lo, hi, a2[0]);
            float pre0 = __uint_as_float(lo) + gx1lo;
            float pre1 = __uint_as_float(hi) + gx1hi;
            float s0 = 1.f / (1.f + __expf(-pre0));
            float s1 = 1.f / (1.f + __expf(-pre1));
            int bA = 2 * bp, bB = 2 * bp + 1;
            if (gate1 == 0) {
                z_s[bA * JC + jl_o] = s0;
                z_s[bB * JC + jl_o] = s1;
            } else {
                float rh0 = s0 * hbuf[(j0 + jl_o) * HPAD + bA];
                float rh1 = s1 * hbuf[(j0 + jl_o) * HPAD + bB];
                __stcg(&g_rh[(size_t)(b0 + bA) * HH + j0 + jl_o], rh0);
                __stcg(&g_rh[(size_t)(b0 + bB) * HH + j0 + jl_o], rh1);
            }
        }

        slot_arrive(grp, rank, 2u * t + 1u);
        slot_wait(grp, 2u * t + 1u);

        // ================= stage 2: fill hbuf with r*h =================
        {
            float4 rv[4];
#pragma unroll
            for (int o = 0; o < 4; o++)
                rv[o] = __ldcg((const float4*)&g_rh[(size_t)(b0 + fb) * HH + (o * 32 + fk) * 4]);
#pragma unroll
            for (int o = 0; o < 4; o++) {
                int k = (o * 32 + fk) * 4;
                hbuf[(k + 0) * HPAD + fb] = rv[o].x;
                hbuf[(k + 1) * HPAD + fb] = rv[o].y;
                hbuf[(k + 2) * HPAD + fb] = rv[o].z;
                hbuf[(k + 3) * HPAD + fb] = rv[o].w;
            }
        }
        __syncthreads();

        // stage-2 dot (K/2 per warp)
#pragma unroll
        for (int v = 0; v < 32; v++) a2[v] = 0ull;
        {
            const int k0 = khalf * 256 + lane;
            const float4* wp = (const float4*)(whs + k0 * JC);
            const char*   hp = (const char*)(hbuf + k0 * HPAD);
#pragma unroll
            for (int i = 0; i < 8; i++) {
                float4 w0 = wp[slotA], w1 = wp[slotB];
                ulonglong2 hL = *(const ulonglong2*)hp;
                ulonglong2 hH = *(const ulonglong2*)(hp + 16);
                unsigned long long hb[4] = {hL.x, hL.y, hH.x, hH.y};
                unsigned long long wd[8];
                DUP_X2(wd[0], w0.x); DUP_X2(wd[1], w0.y);
                DUP_X2(wd[2], w0.z); DUP_X2(wd[3], w0.w);
                DUP_X2(wd[4], w1.x); DUP_X2(wd[5], w1.y);
                DUP_X2(wd[6], w1.z); DUP_X2(wd[7], w1.w);
#pragma unroll
                for (int p = 0; p < 4; p++)
#pragma unroll
                    for (int j = 0; j < 8; j++)
                        FMA_X2(a2[p * 8 + j], hb[p], wd[j], a2[p * 8 + j]);
                wp += 32 * JC / 4;
                hp += 32 * HPAD * 4;
            }
        }
#pragma unroll
        for (int s = 0; s < 5; s++) {
            const int m = 16 >> s, half = 16 >> s;
            bool up = (lane & m) != 0;
#pragma unroll
            for (int i = 0; i < half; i++) {
                unsigned long long send = up ? a2[i] : a2[i + half];
                unsigned long long r = __shfl_xor_sync(0xffffffffu, send, m);
                unsigned long long keep = up ? a2[i + half] : a2[i];
                ADD_X2(a2[i], keep, r);
            }
        }
        if (khalf == 1) partU[jt * 32 + lane] = a2[0];
        __syncthreads();
        if (khalf == 0) {
            unsigned long long tot;
            ADD_X2(tot, a2[0], partU[jt * 32 + lane]);
            unsigned lo, hi;
            UNPACK_X2(lo, hi, tot);
            int bA = 2 * bp, bB = 2 * bp + 1;
            float ht0 = tanhf(__uint_as_float(lo) + gx2lo);
            float ht1 = tanhf(__uint_as_float(hi) + gx2hi);
            float z0 = z_s[bA * JC + jl_o], z1 = z_s[bB * JC + jl_o];
            float o0 = ho_s[bA * JC + jl_o], o1 = ho_s[bB * JC + jl_o];
            float hn0 = o0 + z0 * (ht0 - o0);
            float hn1 = o1 + z1 * (ht1 - o1);
            __stcg(&g_h[(size_t)(b0 + bA) * HH + j0 + jl_o], hn0);
            __stcg(&g_h[(size_t)(b0 + bB) * HH + j0 + jl_o], hn1);
            out[((size_t)t * BB + b0 + bA) * HH + j0 + jl_o] = hn0;
            out[((size_t)t * BB + b0 + bB) * HH + j0 + jl_o] = hn1;
        }

        slot_arrive(grp, rank, 2u * t + 2u);

        // next-step Gx prefetch in the barrier-2 shadow
        if (t + 1 < TT) {
            size_t r1 = (((size_t)(t + 1) * 3 + gate1) * BB + b0 + 2 * bp) * HH + j0 + jl_o;
            gx1lo = __ldg(&g_Gx[r1]);
            gx1hi = __ldg(&g_Gx[r1 + HH]);
            if (khalf == 0) {
                size_t r2 = (((size_t)(t + 1) * 3 + 2) * BB + b0 + 2 * bp) * HH + j0 + jl_o;
                gx2lo = __ldg(&g_Gx[r2]);
                gx2hi = __ldg(&g_Gx[r2 + HH]);
            }
        }

        slot_wait(grp, 2u * t + 2u);
    }
}

// =====================================================================================
extern "C" void kernel_launch(void* const* d_in, const int* in_sizes, int n_in,
                              void* d_out, int out_size)
{
    const float* x  = (const float*)d_in[0];
    const float* h0 = (const float*)d_in[1];
    const float* Wz = (const float*)d_in[2];
    const float* bz = (const float*)d_in[3];
    const float* Wr = (const float*)d_in[4];
    const float* br = (const float*)d_in[5];
    const float* Wh = (const float*)d_in[6];
    const float* bh = (const float*)d_in[7];
    float* out = (float*)d_out;

    const int smem_bytes = (3 * HH * JC + HH * HPAD + 2 * GB * JC) * (int)sizeof(float)
                         + 4 * 32 * (int)sizeof(unsigned long long);
    cudaFuncSetAttribute(phase2_gru, cudaFuncAttributeMaxDynamicSharedMemorySize, smem_bytes);

    dim3 g1((TT * BB) / 128, 24);
    phase1_gemm<<<g1, 256>>>(x, Wz, bz, Wr, br, Wh, bh);

    phase2_gru<<<NGROUPS * GC, NT, smem_bytes>>>(h0, Wz, Wr, Wh, out);
}

// round 14
// speedup vs baseline: 1.6896x; 1.6896x over previous
#include <cuda_runtime.h>
#include <math.h>
#include <stdint.h>

#define TT 2048
#define BB 64
#define DD 256
#define HH 512

#define NGROUPS 8
#define GC 32         // CTAs per group (32 x 16 cols = 512)
#define GB 8          // batch elems per group
#define JC 16         // output columns owned per CTA
#define NT 128        // 4 warps; 2 CTAs co-resident per SM

// ---------------- packed fp32x2 helpers ----------------
#define FMA_X2(d, a, b, c) \
    asm("fma.rn.f32x2 %0, %1, %2, %3;" : "=l"(d) : "l"(a), "l"(b), "l"(c))
#define ADD_X2(d, a, b) \
    asm("add.rn.f32x2 %0, %1, %2;" : "=l"(d) : "l"(a), "l"(b))
#define DUP_X2(d, s) \
    asm("mov.b64 %0, {%1, %1};" : "=l"(d) : "r"(__float_as_uint(s)))
#define UNPACK_X2(lo, hi, p) \
    asm("mov.b64 {%0, %1}, %2;" : "=r"(lo), "=r"(hi) : "l"(p))
#define PACK_X2(d, lo, hi) \
    asm("mov.b64 %0, {%1, %2};" : "=l"(d) : "f"(lo), "f"(hi))

// ---------------- device scratch ----------------
__device__ float g_Gx[(size_t)TT * 3 * BB * HH];
__device__ float g_h[BB * HH];
__device__ float g_rh[BB * HH];
__device__ unsigned g_bcnt[NGROUPS];
__device__ unsigned g_bgen[NGROUPS];

// ---------------- group barrier (R5-proven: acq/rel atomics, generation) ------------
__device__ __forceinline__ void group_barrier(int grp) {
    __syncthreads();
    if (threadIdx.x == 0) {
        unsigned gen;
        asm volatile("ld.acquire.gpu.global.u32 %0, [%1];"
                     : "=r"(gen) : "l"(&g_bgen[grp]));
        unsigned old;
        asm volatile("atom.acq_rel.gpu.global.add.u32 %0, [%1], %2;"
                     : "=r"(old) : "l"(&g_bcnt[grp]), "r"(1u));
        if (old == GC - 1u) {
            asm volatile("st.relaxed.gpu.global.u32 [%0], %1;"
                         :: "l"(&g_bcnt[grp]), "r"(0u));
            asm volatile("st.release.gpu.global.u32 [%0], %1;"
                         :: "l"(&g_bgen[grp]), "r"(gen + 1u));
        } else {
            unsigned cur;
            do {
                asm volatile("ld.acquire.gpu.global.u32 %0, [%1];"
                             : "=r"(cur) : "l"(&g_bgen[grp]));
            } while (cur == gen);
        }
    }
    __syncthreads();
}

// =====================================================================================
// Phase 1 (R5-proven, unchanged)
// =====================================================================================
__global__ void __launch_bounds__(256) phase1_gemm(
    const float* __restrict__ x,
    const float* __restrict__ Wz, const float* __restrict__ bz,
    const float* __restrict__ Wr, const float* __restrict__ br,
    const float* __restrict__ Wh, const float* __restrict__ bh)
{
    __shared__ float xs[32 * 132];
    __shared__ float ws[32 * 64];

    const int gate = blockIdx.y >> 3;
    const int jt0  = (blockIdx.y & 7) * 64;
    const float* W    = (gate == 0) ? Wz : ((gate == 1) ? Wr : Wh);
    const float* bias = (gate == 0) ? bz : ((gate == 1) ? br : bh);
    const int m0  = blockIdx.x * 128;
    const int tid = threadIdx.x;
    const int tn = tid & 15;
    const int tm = tid >> 4;

    unsigned long long pa[4][4];
#pragma unroll
    for (int i = 0; i < 4; i++)
#pragma unroll
        for (int j = 0; j < 4; j++) pa[i][j] = 0ull;

    for (int kc = 0; kc < 8; kc++) {
#pragma unroll
        for (int i = 0; i < 16; i++) {
            int idx = tid + i * 256;
            int row = idx >> 5, kk = idx & 31;
            xs[kk * 132 + row] = x[(size_t)(m0 + row) * DD + kc * 32 + kk];
        }
#pragma unroll
        for (int i = 0; i < 8; i++) {
            int idx = tid + i * 256;
            int kk = idx >> 6, jj = idx & 63;
            ws[kk * 64 + jj] = W[(size_t)(kc * 32 + kk) * HH + jt0 + jj];
        }
        __syncthreads();
#pragma unroll 8
        for (int kk = 0; kk < 32; kk++) {
            float4 w4 = *(const float4*)&ws[kk * 64 + tn * 4];
            ulonglong2 xL = *(const ulonglong2*)&xs[kk * 132 + tm * 8];
            ulonglong2 xH = *(const ulonglong2*)&xs[kk * 132 + tm * 8 + 4];
            unsigned long long hp[4] = {xL.x, xL.y, xH.x, xH.y};
            unsigned long long wd[4];
            DUP_X2(wd[0], w4.x); DUP_X2(wd[1], w4.y);
            DUP_X2(wd[2], w4.z); DUP_X2(wd[3], w4.w);
#pragma unroll
            for (int i = 0; i < 4; i++)
#pragma unroll
                for (int j = 0; j < 4; j++)
                    FMA_X2(pa[i][j], hp[i], wd[j], pa[i][j]);
        }
        __syncthreads();
    }

#pragma unroll
    for (int i = 0; i < 4; i++) {
#pragma unroll
        for (int j = 0; j < 4; j++) {
            unsigned lo, hi;
            UNPACK_X2(lo, hi, pa[i][j]);
            float bj = bias[jt0 + tn * 4 + j];
            int mA = m0 + tm * 8 + 2 * i;
            int tA = mA >> 6, bA = mA & 63;
            g_Gx[(((size_t)tA * 3 + gate) * BB + bA) * HH + jt0 + tn * 4 + j] =
                __uint_as_float(lo) + bj;
            int mB = mA + 1;
            int tB = mB >> 6, bB = mB & 63;
            g_Gx[(((size_t)tB * 3 + gate) * BB + bB) * HH + jt0 + tn * 4 + j] =
                __uint_as_float(hi) + bj;
        }
    }
}

// =====================================================================================
// Phase 2: persistent GRU, 256 CTAs (2/SM), 8 groups x 32 CTAs, GB=8, JC=16, NT=128.
// h/rh in pair-split arrays: LO = pairs (b0,b1),(b2,b3), HI = (b4,b5),(b6,b7);
// 16B rows -> one ulonglong2 per (array,k): conflict-free by construction.
// Weights [512][16], 4 float4 slots/row, phys slot = logical ^ ((k>>1)&3);
// reader swizzle sw = (lane>>1)&3 (hoisted: k = lane + 32i keeps (k>>1)&3 constant).
// Stage1: warp w -> gate=w>>1 (0=z,1=r), jt=w&1 (8 cols), full K=512.
// Stage2: warp w -> khalf=w>>1 (K/2),    jt=w&1 (8 cols), smem combine.
// R5 butterfly verbatim (32 packed vals, splits m=16,8,4,2,1) -> lane owns v=lane:
//   bp = lane>>3 (b-pair), jl_o = jt*8 + (lane&7).
// z and h_old live in REGISTERS on warps 0,1 (same threads compute z and update h).
// =====================================================================================
#define PA_LO 98304   // byte offset of LO pair array (512 rows x 16B)
#define PA_HI 106496  // HI pair array
#define PA_PART 114688 // partU [2][32] u64
#define SMEM_P2 115200

__global__ void __launch_bounds__(NT, 2) phase2_gru(
    const float* __restrict__ h0in,
    const float* __restrict__ Wz,
    const float* __restrict__ Wr,
    const float* __restrict__ Wh,
    float* __restrict__ out)
{
    extern __shared__ char smc[];
    float* wzs = (float*)smc;               // [512][16] swizzled
    float* wrs = wzs + HH * JC;
    float* whs = wrs + HH * JC;
    char* paLO = smc + PA_LO;
    char* paHI = smc + PA_HI;
    unsigned long long* partU = (unsigned long long*)(smc + PA_PART);

    const int grp  = blockIdx.x >> 5;
    const int rank = blockIdx.x & 31;
    const int b0 = grp * GB;
    const int j0 = rank * JC;
    const int tid  = threadIdx.x;
    const int warp = tid >> 5;
    const int lane = tid & 31;

    // resident recurrent weights (rows DD..DD+511), 2-bit float4-slot swizzle
    for (int m = 0; m < 3; m++) {
        const float* Wsrc = (m == 0) ? Wz : ((m == 1) ? Wr : Wh);
        float* wdst = (m == 0) ? wzs : ((m == 1) ? wrs : whs);
        for (int idx = tid; idx < HH * JC; idx += NT) {
            int k = idx >> 4, jl = idx & 15;
            int phys = k * JC + (((jl >> 2) ^ ((k >> 1) & 3)) << 2) + (jl & 3);
            wdst[phys] = Wsrc[(size_t)(DD + k) * HH + j0 + jl];
        }
    }
    group_barrier(grp);

    const int gate1 = warp >> 1;             // stage1: 0=z, 1=r
    const int jt    = warp & 1;              // 8-col tile (both stages)
    const int khalf = warp >> 1;             // stage2 k-half
    const int sw    = (lane >> 1) & 3;
    const int slotA = (jt * 2) ^ sw;
    const int slotB = (jt * 2 + 1) ^ sw;
    const int bp    = lane >> 3;             // owned b-pair (R5 mapping)
    const int jl_o  = jt * 8 + (lane & 7);   // owned column
    const int bA = 2 * bp, bB = 2 * bp + 1;
    // pair-array address of own (column, pair) element
    char* ownArr = ((bp < 2) ? paLO : paHI) + (size_t)(j0 + jl_o) * 16 + (bp & 1) * 8;
    // fill mapping: warp-half -> LO/HI, 64 threads per array, 8 k's per thread
    const int fhalf = warp >> 1;
    const int fbase = b0 + fhalf * 4;
    const int fk    = ((warp & 1) * 32 + lane) * 8;
    char* fArr = (fhalf == 0) ? paLO : paHI;

    for (int t = 0; t < TT; t++) {
        // ---- Gx prefetch (R5 pattern) ----
        float gx1lo, gx1hi, gx2lo = 0.f, gx2hi = 0.f;
        {
            size_t r1 = (((size_t)t * 3 + gate1) * BB + b0 + bA) * HH + j0 + jl_o;
            gx1lo = __ldg(&g_Gx[r1]);
            gx1hi = __ldg(&g_Gx[r1 + HH]);
            if (khalf == 0) {
                size_t r2 = (((size_t)t * 3 + 2) * BB + b0 + bA) * HH + j0 + jl_o;
                gx2lo = __ldg(&g_Gx[r2]);
                gx2hi = __ldg(&g_Gx[r2 + HH]);
            }
        }

        // ---- fill pair arrays with h ----
        const float* hsrc = (t == 0) ? h0in : (const float*)g_h;
        {
            float4 r0a = __ldcg((const float4*)&hsrc[(size_t)(fbase + 0) * HH + fk]);
            float4 r0b = __ldcg((const float4*)&hsrc[(size_t)(fbase + 0) * HH + fk + 4]);
            float4 r1a = __ldcg((const float4*)&hsrc[(size_t)(fbase + 1) * HH + fk]);
            float4 r1b = __ldcg((const float4*)&hsrc[(size_t)(fbase + 1) * HH + fk + 4]);
            float4 r2a = __ldcg((const float4*)&hsrc[(size_t)(fbase + 2) * HH + fk]);
            float4 r2b = __ldcg((const float4*)&hsrc[(size_t)(fbase + 2) * HH + fk + 4]);
            float4 r3a = __ldcg((const float4*)&hsrc[(size_t)(fbase + 3) * HH + fk]);
            float4 r3b = __ldcg((const float4*)&hsrc[(size_t)(fbase + 3) * HH + fk + 4]);
            const float* p0a = &r0a.x; const float* p1a = &r1a.x;
            const float* p2a = &r2a.x; const float* p3a = &r3a.x;
            const float* p0b = &r0b.x; const float* p1b = &r1b.x;
            const float* p2b = &r2b.x; const float* p3b = &r3b.x;
#pragma unroll
            for (int j = 0; j < 4; j++) {
                ulonglong2 u;
                PACK_X2(u.x, p0a[j], p1a[j]);
                PACK_X2(u.y, p2a[j], p3a[j]);
                *(ulonglong2*)(fArr + (size_t)(fk + j) * 16) = u;
                ulonglong2 v;
                PACK_X2(v.x, p0b[j], p1b[j]);
                PACK_X2(v.y, p2b[j], p3b[j]);
                *(ulonglong2*)(fArr + (size_t)(fk + 4 + j) * 16) = v;
            }
        }
        __syncthreads();

        // h_old for own (pair, column) -> registers (kept through the step)
        float ho0, ho1;
        {
            unsigned long long hv = *(const unsigned long long*)ownArr;
            unsigned l_, h_;
            UNPACK_X2(l_, h_, hv);
            ho0 = __uint_as_float(l_);
            ho1 = __uint_as_float(h_);
        }

        // ================= stage 1 dot (full K=512 per warp) =================
        unsigned long long a2[32];
#pragma unroll
        for (int v = 0; v < 32; v++) a2[v] = 0ull;
        {
            const float4* wp = (const float4*)((gate1 ? wrs : wzs) + lane * JC);
            const char*   lo = paLO + lane * 16;
            const char*   hi = paHI + lane * 16;
#pragma unroll
            for (int i = 0; i < 16; i++) {
                float4 w0 = wp[slotA], w1 = wp[slotB];
                ulonglong2 hL = *(const ulonglong2*)lo;
                ulonglong2 hH = *(const ulonglong2*)hi;
                unsigned long long hb[4] = {hL.x, hL.y, hH.x, hH.y};
                unsigned long long wd[8];
                DUP_X2(wd[0], w0.x); DUP_X2(wd[1], w0.y);
                DUP_X2(wd[2], w0.z); DUP_X2(wd[3], w0.w);
                DUP_X2(wd[4], w1.x); DUP_X2(wd[5], w1.y);
                DUP_X2(wd[6], w1.z); DUP_X2(wd[7], w1.w);
#pragma unroll
                for (int p = 0; p < 4; p++)
#pragma unroll
                    for (int j = 0; j < 8; j++)
                        FMA_X2(a2[p * 8 + j], hb[p], wd[j], a2[p * 8 + j]);
                wp += 32 * JC / 4;
                lo += 32 * 16;
                hi += 32 * 16;
            }
        }
        // R5 butterfly (verbatim): lane ends owning v = lane
#pragma unroll
        for (int s = 0; s < 5; s++) {
            const int m = 16 >> s, half = 16 >> s;
            bool up = (lane & m) != 0;
#pragma unroll
            for (int i = 0; i < half; i++) {
                unsigned long long send = up ? a2[i] : a2[i + half];
                unsigned long long r = __shfl_xor_sync(0xffffffffu, send, m);
                unsigned long long keep = up ? a2[i + half] : a2[i];
                ADD_X2(a2[i], keep, r);
            }
        }
        float z0 = 0.f, z1 = 0.f;
        {
            unsigned lo_, hi_;
            UNPACK_X2(lo_, hi_, a2[0]);
            float s0 = 1.f / (1.f + __expf(-(__uint_as_float(lo_) + gx1lo)));
            float s1 = 1.f / (1.f + __expf(-(__uint_as_float(hi_) + gx1hi)));
            if (gate1 == 0) {
                z0 = s0; z1 = s1;              // stays in registers (same warps update h)
            } else {
                __stcg(&g_rh[(size_t)(b0 + bA) * HH + j0 + jl_o], s0 * ho0);
                __stcg(&g_rh[(size_t)(b0 + bB) * HH + j0 + jl_o], s1 * ho1);
            }
        }

        group_barrier(grp);   // rh complete group-wide

        // ================= stage 2: fill pair arrays with r*h =================
        {
            float4 r0a = __ldcg((const float4*)&g_rh[(size_t)(fbase + 0) * HH + fk]);
            float4 r0b = __ldcg((const float4*)&g_rh[(size_t)(fbase + 0) * HH + fk + 4]);
            float4 r1a = __ldcg((const float4*)&g_rh[(size_t)(fbase + 1) * HH + fk]);
            float4 r1b = __ldcg((const float4*)&g_rh[(size_t)(fbase + 1) * HH + fk + 4]);
            float4 r2a = __ldcg((const float4*)&g_rh[(size_t)(fbase + 2) * HH + fk]);
            float4 r2b = __ldcg((const float4*)&g_rh[(size_t)(fbase + 2) * HH + fk + 4]);
            float4 r3a = __ldcg((const float4*)&g_rh[(size_t)(fbase + 3) * HH + fk]);
            float4 r3b = __ldcg((const float4*)&g_rh[(size_t)(fbase + 3) * HH + fk + 4]);
            const float* p0a = &r0a.x; const float* p1a = &r1a.x;
            const float* p2a = &r2a.x; const float* p3a = &r3a.x;
            const float* p0b = &r0b.x; const float* p1b = &r1b.x;
            const float* p2b = &r2b.x; const float* p3b = &r3b.x;
#pragma unroll
            for (int j = 0; j < 4; j++) {
                ulonglong2 u;
                PACK_X2(u.x, p0a[j], p1a[j]);
                PACK_X2(u.y, p2a[j], p3a[j]);
                *(ulonglong2*)(fArr + (size_t)(fk + j) * 16) = u;
                ulonglong2 v;
                PACK_X2(v.x, p0b[j], p1b[j]);
                PACK_X2(v.y, p2b[j], p3b[j]);
                *(ulonglong2*)(fArr + (size_t)(fk + 4 + j) * 16) = v;
            }
        }
        __syncthreads();

        // stage-2 dot (K/2 per warp)
#pragma unroll
        for (int v = 0; v < 32; v++) a2[v] = 0ull;
        {
            const int k0 = khalf * 256 + lane;
            const float4* wp = (const float4*)(whs + k0 * JC);
            const char*   lo = paLO + k0 * 16;
            const char*   hi = paHI + k0 * 16;
#pragma unroll
            for (int i = 0; i < 8; i++) {
                float4 w0 = wp[slotA], w1 = wp[slotB];
                ulonglong2 hL = *(const ulonglong2*)lo;
                ulonglong2 hH = *(const ulonglong2*)hi;
                unsigned long long hb[4] = {hL.x, hL.y, hH.x, hH.y};
                unsigned long long wd[8];
                DUP_X2(wd[0], w0.x); DUP_X2(wd[1], w0.y);
                DUP_X2(wd[2], w0.z); DUP_X2(wd[3], w0.w);
                DUP_X2(wd[4], w1.x); DUP_X2(wd[5], w1.y);
                DUP_X2(wd[6], w1.z); DUP_X2(wd[7], w1.w);
#pragma unroll
                for (int p = 0; p < 4; p++)
#pragma unroll
                    for (int j = 0; j < 8; j++)
                        FMA_X2(a2[p * 8 + j], hb[p], wd[j], a2[p * 8 + j]);
                wp += 32 * JC / 4;
                lo += 32 * 16;
                hi += 32 * 16;
            }
        }
#pragma unroll
        for (int s = 0; s < 5; s++) {
            const int m = 16 >> s, half = 16 >> s;
            bool up = (lane & m) != 0;
#pragma unroll
            for (int i = 0; i < half; i++) {
                unsigned long long send = up ? a2[i] : a2[i + half];
                unsigned long long r = __shfl_xor_sync(0xffffffffu, send, m);
                unsigned long long keep = up ? a2[i + half] : a2[i];
                ADD_X2(a2[i], keep, r);
            }
        }
        // cross-khalf combine + update epilogue (warps 0,1 hold z/ho in regs)
        if (khalf == 1) partU[jt * 32 + lane] = a2[0];
        __syncthreads();
        if (khalf == 0) {
            unsigned long long tot;
            ADD_X2(tot, a2[0], partU[jt * 32 + lane]);
            unsigned lo_, hi_;
            UNPACK_X2(lo_, hi_, tot);
            float ht0 = tanhf(__uint_as_float(lo_) + gx2lo);
            float ht1 = tanhf(__uint_as_float(hi_) + gx2hi);
            float hn0 = ho0 + z0 * (ht0 - ho0);
            float hn1 = ho1 + z1 * (ht1 - ho1);
            __stcg(&g_h[(size_t)(b0 + bA) * HH + j0 + jl_o], hn0);
            __stcg(&g_h[(size_t)(b0 + bB) * HH + j0 + jl_o], hn1);
            out[((size_t)t * BB + b0 + bA) * HH + j0 + jl_o] = hn0;
            out[((size_t)t * BB + b0 + bB) * HH + j0 + jl_o] = hn1;
        }

        group_barrier(grp);   // h complete before next step
    }
}

// =====================================================================================
extern "C" void kernel_launch(void* const* d_in, const int* in_sizes, int n_in,
                              void* d_out, int out_size)
{
    const float* x  = (const float*)d_in[0];
    const float* h0 = (const float*)d_in[1];
    const float* Wz = (const float*)d_in[2];
    const float* bz = (const float*)d_in[3];
    const float* Wr = (const float*)d_in[4];
    const float* br = (const float*)d_in[5];
    const float* Wh = (const float*)d_in[6];
    const float* bh = (const float*)d_in[7];
    float* out = (float*)d_out;

    cudaFuncSetAttribute(phase2_gru, cudaFuncAttributeMaxDynamicSharedMemorySize, SMEM_P2);

    dim3 g1((TT * BB) / 128, 24);
    phase1_gemm<<<g1, 256>>>(x, Wz, bz, Wr, br, Wh, bh);

    phase2_gru<<<NGROUPS * GC, NT, SMEM_P2>>>(h0, Wz, Wr, Wh, out);
}

// round 15
// speedup vs baseline: 2.1738x; 1.2866x over previous
#include <cuda_runtime.h>
#include <math.h>

#define TT 2048
#define BB 64
#define DD 256
#define HH 512

#define NGROUPS 8
#define GC 16         // CTAs per group
#define GB 8          // batch elems per group
#define JC 32         // output columns owned per CTA
#define NT 256        // 8 warps
#define HPAD 12       // hbuf row pad (16B-aligned rows, conflict-free LDS.128)

// ---------------- packed fp32x2 helpers ----------------
#define FMA_X2(d, a, b, c) \
    asm("fma.rn.f32x2 %0, %1, %2, %3;" : "=l"(d) : "l"(a), "l"(b), "l"(c))
#define ADD_X2(d, a, b) \
    asm("add.rn.f32x2 %0, %1, %2;" : "=l"(d) : "l"(a), "l"(b))
#define DUP_X2(d, s) \
    asm("mov.b64 %0, {%1, %1};" : "=l"(d) : "r"(__float_as_uint(s)))
#define UNPACK_X2(lo, hi, p) \
    asm("mov.b64 {%0, %1}, %2;" : "=r"(lo), "=r"(hi) : "l"(p))

// ---------------- device scratch ----------------
__device__ float g_Gx[(size_t)TT * 3 * BB * HH];
__device__ float g_h[BB * HH];
__device__ float g_rh[BB * HH];
__device__ unsigned g_bcnt[NGROUPS];   // monotonic arrive counter
__device__ unsigned g_bgen[NGROUPS];   // monotonic generation

// ---------------- slim group barrier: monotonic, no gen preload, no reset ------------
__device__ __forceinline__ void group_barrier(int grp) {
    __syncthreads();
    if (threadIdx.x == 0) {
        unsigned old;
        asm volatile("atom.acq_rel.gpu.global.add.u32 %0, [%1], %2;"
                     : "=r"(old) : "l"(&g_bcnt[grp]), "r"(1u));
        unsigned target = old / GC + 1u;
        if (old % GC == GC - 1u) {
            asm volatile("st.release.gpu.global.u32 [%0], %1;"
                         :: "l"(&g_bgen[grp]), "r"(target));
        } else {
            unsigned cur;
            do {
                asm volatile("ld.acquire.gpu.global.u32 %0, [%1];"
                             : "=r"(cur) : "l"(&g_bgen[grp]));
            } while (cur < target);
        }
    }
    __syncthreads();
}

// ---------------- fast activations (errors ~1e-6; huge margin vs 1e-3) ---------------
__device__ __forceinline__ float fast_sigmoid(float x) {
    return __fdividef(1.f, 1.f + __expf(-x));
}
__device__ __forceinline__ float fast_tanh(float x) {
    return __fdividef(2.f, 1.f + __expf(-2.f * x)) - 1.f;
}

// =====================================================================================
// Phase 1 (R5-proven, unchanged)
// =====================================================================================
__global__ void __launch_bounds__(256) phase1_gemm(
    const float* __restrict__ x,
    const float* __restrict__ Wz, const float* __restrict__ bz,
    const float* __restrict__ Wr, const float* __restrict__ br,
    const float* __restrict__ Wh, const float* __restrict__ bh)
{
    __shared__ float xs[32 * 132];
    __shared__ float ws[32 * 64];

    const int gate = blockIdx.y >> 3;
    const int jt0  = (blockIdx.y & 7) * 64;
    const float* W    = (gate == 0) ? Wz : ((gate == 1) ? Wr : Wh);
    const float* bias = (gate == 0) ? bz : ((gate == 1) ? br : bh);
    const int m0  = blockIdx.x * 128;
    const int tid = threadIdx.x;
    const int tn = tid & 15;
    const int tm = tid >> 4;

    unsigned long long pa[4][4];
#pragma unroll
    for (int i = 0; i < 4; i++)
#pragma unroll
        for (int j = 0; j < 4; j++) pa[i][j] = 0ull;

    for (int kc = 0; kc < 8; kc++) {
#pragma unroll
        for (int i = 0; i < 16; i++) {
            int idx = tid + i * 256;
            int row = idx >> 5, kk = idx & 31;
            xs[kk * 132 + row] = x[(size_t)(m0 + row) * DD + kc * 32 + kk];
        }
#pragma unroll
        for (int i = 0; i < 8; i++) {
            int idx = tid + i * 256;
            int kk = idx >> 6, jj = idx & 63;
            ws[kk * 64 + jj] = W[(size_t)(kc * 32 + kk) * HH + jt0 + jj];
        }
        __syncthreads();
#pragma unroll 8
        for (int kk = 0; kk < 32; kk++) {
            float4 w4 = *(const float4*)&ws[kk * 64 + tn * 4];
            ulonglong2 xL = *(const ulonglong2*)&xs[kk * 132 + tm * 8];
            ulonglong2 xH = *(const ulonglong2*)&xs[kk * 132 + tm * 8 + 4];
            unsigned long long hp[4] = {xL.x, xL.y, xH.x, xH.y};
            unsigned long long wd[4];
            DUP_X2(wd[0], w4.x); DUP_X2(wd[1], w4.y);
            DUP_X2(wd[2], w4.z); DUP_X2(wd[3], w4.w);
#pragma unroll
            for (int i = 0; i < 4; i++)
#pragma unroll
                for (int j = 0; j < 4; j++)
                    FMA_X2(pa[i][j], hp[i], wd[j], pa[i][j]);
        }
        __syncthreads();
    }

#pragma unroll
    for (int i = 0; i < 4; i++) {
#pragma unroll
        for (int j = 0; j < 4; j++) {
            unsigned lo, hi;
            UNPACK_X2(lo, hi, pa[i][j]);
            float bj = bias[jt0 + tn * 4 + j];
            int mA = m0 + tm * 8 + 2 * i;
            int tA = mA >> 6, bA = mA & 63;
            g_Gx[(((size_t)tA * 3 + gate) * BB + bA) * HH + jt0 + tn * 4 + j] =
                __uint_as_float(lo) + bj;
            int mB = mA + 1;
            int tB = mB >> 6, bB = mB & 63;
            g_Gx[(((size_t)tB * 3 + gate) * BB + bB) * HH + jt0 + tn * 4 + j] =
                __uint_as_float(hi) + bj;
        }
    }
}

// =====================================================================================
// Phase 2: R5 skeleton. Stage1 unchanged (gate=w>>2, jt=w&3, full K, 32-val butterfly).
// Stage2 NEW: warp w owns cols [4w, 4w+4), FULL K=512, 16 packed acc, pre-stage(m=16)
// + 4 splitting stages -> lanes<16 own v=lane (p=lane>>2, c=lane&3). No partU/combine.
// Slim monotonic barrier. Fast sigmoid/tanh.
// =====================================================================================
__global__ void __launch_bounds__(NT, 1) phase2_gru(
    const float* __restrict__ h0in,
    const float* __restrict__ Wz,
    const float* __restrict__ Wr,
    const float* __restrict__ Wh,
    float* __restrict__ out)
{
    extern __shared__ float sm[];
    float* wzs  = sm;                     // [512][32] swizzled
    float* wrs  = wzs + HH * JC;
    float* whs  = wrs + HH * JC;
    float* hbuf = whs + HH * JC;          // [512][HPAD]
    float* z_s  = hbuf + HH * HPAD;       // [8][32]
    float* ho_s = z_s + GB * JC;          // [8][32]

    const int grp  = blockIdx.x >> 4;
    const int rank = blockIdx.x & 15;
    const int b0 = grp * GB;
    const int j0 = rank * JC;
    const int tid  = threadIdx.x;
    const int warp = tid >> 5;
    const int lane = tid & 31;

    // resident recurrent weights (rows DD..DD+511), float4-slot XOR swizzle
    for (int idx = tid; idx < HH * JC; idx += NT) {
        int k = idx >> 5, jl = idx & 31;
        int phys = k * JC + ((((jl >> 2) ^ (k & 7))) << 2) + (jl & 3);
        size_t goff = (size_t)(DD + k) * HH + j0 + jl;
        wzs[phys] = Wz[goff];
        wrs[phys] = Wr[goff];
        whs[phys] = Wh[goff];
    }
    __syncthreads();

    const int gate1 = warp >> 2;            // stage1: 0=z, 1=r
    const int jt    = warp & 3;             // stage1 8-col tile
    const int slotA = (jt * 2) ^ (lane & 7);
    const int slotB = (jt * 2 + 1) ^ (lane & 7);
    const int slot2 = warp ^ (lane & 7);    // stage2: warp's 4-col float4 slot
    const int bp    = lane >> 3;            // stage1 owned b-pair
    const int jl_o  = jt * 8 + (lane & 7);  // stage1 owned column
    const int p2    = (lane & 15) >> 2;     // stage2 owned b-pair (lanes<16)
    const int c2    = warp * 4 + (lane & 3);// stage2 owned column

    for (int t = 0; t < TT; t++) {
        // ---- Gx prefetch (DRAM latency hidden under fill+dot1) ----
        float gx1lo, gx1hi, gx2lo = 0.f, gx2hi = 0.f;
        {
            size_t r1 = (((size_t)t * 3 + gate1) * BB + b0 + 2 * bp) * HH + j0 + jl_o;
            gx1lo = __ldg(&g_Gx[r1]);
            gx1hi = __ldg(&g_Gx[r1 + HH]);
            if (lane < 16) {
                size_t r2 = (((size_t)t * 3 + 2) * BB + b0 + 2 * p2) * HH + j0 + c2;
                gx2lo = __ldg(&g_Gx[r2]);
                gx2hi = __ldg(&g_Gx[r2 + HH]);
            }
        }

        // ---- fill hbuf with h (R5-proven scalar pattern, 4-way STS max) ----
        const float* hsrc = (t == 0) ? h0in : (const float*)g_h;
#pragma unroll
        for (int q = 0; q < 2; q++) {
            int kk = tid + q * NT;
#pragma unroll
            for (int b = 0; b < GB; b++)
                hbuf[kk * HPAD + b] = __ldcg(&hsrc[(size_t)(b0 + b) * HH + kk]);
        }
        __syncthreads();

        // stash h_old for own columns
        { int b = tid >> 5, jl = tid & 31; ho_s[tid] = hbuf[(j0 + jl) * HPAD + b]; }

        // ================= stage 1 dot (full K=512 per warp) — R5 verbatim =========
        unsigned long long a2[32];
#pragma unroll
        for (int v = 0; v < 32; v++) a2[v] = 0ull;
        {
            const float4* wp = (const float4*)((gate1 ? wrs : wzs) + lane * JC);
            const char*   hp = (const char*)(hbuf + lane * HPAD);
#pragma unroll
            for (int i = 0; i < 16; i++) {
                float4 w0 = wp[slotA], w1 = wp[slotB];
                ulonglong2 hL = *(const ulonglong2*)hp;
                ulonglong2 hH = *(const ulonglong2*)(hp + 16);
                unsigned long long hb[4] = {hL.x, hL.y, hH.x, hH.y};
                unsigned long long wd[8];
                DUP_X2(wd[0], w0.x); DUP_X2(wd[1], w0.y);
                DUP_X2(wd[2], w0.z); DUP_X2(wd[3], w0.w);
                DUP_X2(wd[4], w1.x); DUP_X2(wd[5], w1.y);
                DUP_X2(wd[6], w1.z); DUP_X2(wd[7], w1.w);
#pragma unroll
                for (int p = 0; p < 4; p++)
#pragma unroll
                    for (int j = 0; j < 8; j++)
                        FMA_X2(a2[p * 8 + j], hb[p], wd[j], a2[p * 8 + j]);
                wp += 32 * JC / 4;
                hp += 32 * HPAD * 4;
            }
        }
        // R5 butterfly (32 values, 5 splitting stages): lane owns v = lane
#pragma unroll
        for (int s = 0; s < 5; s++) {
            const int m = 16 >> s, half = 16 >> s;
            bool up = (lane & m) != 0;
#pragma unroll
            for (int i = 0; i < half; i++) {
                unsigned long long send = up ? a2[i] : a2[i + half];
                unsigned long long r = __shfl_xor_sync(0xffffffffu, send, m);
                unsigned long long keep = up ? a2[i + half] : a2[i];
                ADD_X2(a2[i], keep, r);
            }
        }
        {
            unsigned lo, hi;
            UNPACK_X2(lo, hi, a2[0]);
            float s0 = fast_sigmoid(__uint_as_float(lo) + gx1lo);
            float s1 = fast_sigmoid(__uint_as_float(hi) + gx1hi);
            int bA = 2 * bp, bB = 2 * bp + 1;
            if (gate1 == 0) {
                z_s[bA * JC + jl_o] = s0;
                z_s[bB * JC + jl_o] = s1;
            } else {
                float rh0 = s0 * hbuf[(j0 + jl_o) * HPAD + bA];
                float rh1 = s1 * hbuf[(j0 + jl_o) * HPAD + bB];
                __stcg(&g_rh[(size_t)(b0 + bA) * HH + j0 + jl_o], rh0);
                __stcg(&g_rh[(size_t)(b0 + bB) * HH + j0 + jl_o], rh1);
            }
        }

        group_barrier(grp);   // rh complete group-wide

        // ================= stage 2: fill hbuf with r*h (R5 scalar pattern) =========
#pragma unroll
        for (int q = 0; q < 2; q++) {
            int kk = tid + q * NT;
#pragma unroll
            for (int b = 0; b < GB; b++)
                hbuf[kk * HPAD + b] = __ldcg(&g_rh[(size_t)(b0 + b) * HH + kk]);
        }
        __syncthreads();

        // stage-2 dot: warp owns 4 cols, FULL K=512 (no cross-warp combine)
        unsigned long long b2[16];
#pragma unroll
        for (int v = 0; v < 16; v++) b2[v] = 0ull;
        {
            const float4* wp = (const float4*)(whs + lane * JC);
            const char*   hp = (const char*)(hbuf + lane * HPAD);
#pragma unroll
            for (int i = 0; i < 16; i++) {
                float4 w4 = wp[slot2];
                ulonglong2 hL = *(const ulonglong2*)hp;
                ulonglong2 hH = *(const ulonglong2*)(hp + 16);
                unsigned long long hb[4] = {hL.x, hL.y, hH.x, hH.y};
                unsigned long long wd[4];
                DUP_X2(wd[0], w4.x); DUP_X2(wd[1], w4.y);
                DUP_X2(wd[2], w4.z); DUP_X2(wd[3], w4.w);
#pragma unroll
                for (int p = 0; p < 4; p++)
#pragma unroll
                    for (int c = 0; c < 4; c++)
                        FMA_X2(b2[p * 4 + c], hb[p], wd[c], b2[p * 4 + c]);
                wp += 32 * JC / 4;
                hp += 32 * HPAD * 4;
            }
        }
        // R8-validated reduction: pre-stage m=16 (non-splitting) + splits m=8,4,2,1
#pragma unroll
        for (int i = 0; i < 16; i++) {
            unsigned long long r = __shfl_xor_sync(0xffffffffu, b2[i], 16);
            ADD_X2(b2[i], b2[i], r);
        }
#pragma unroll
        for (int s = 0; s < 4; s++) {
            const int m = 8 >> s, half = 8 >> s;
            bool up = (lane & m) != 0;
#pragma unroll
            for (int i = 0; i < half; i++) {
                unsigned long long send = up ? b2[i] : b2[i + half];
                unsigned long long r = __shfl_xor_sync(0xffffffffu, send, m);
                unsigned long long keep = up ? b2[i + half] : b2[i];
                ADD_X2(b2[i], keep, r);
            }
        }
        if (lane < 16) {
            unsigned lo, hi;
            UNPACK_X2(lo, hi, b2[0]);
            int bA = 2 * p2, bB = bA + 1;
            float ht0 = fast_tanh(__uint_as_float(lo) + gx2lo);
            float ht1 = fast_tanh(__uint_as_float(hi) + gx2hi);
            float z0 = z_s[bA * JC + c2], z1 = z_s[bB * JC + c2];
            float o0 = ho_s[bA * JC + c2], o1 = ho_s[bB * JC + c2];
            float hn0 = o0 + z0 * (ht0 - o0);
            float hn1 = o1 + z1 * (ht1 - o1);
            __stcg(&g_h[(size_t)(b0 + bA) * HH + j0 + c2], hn0);
            __stcg(&g_h[(size_t)(b0 + bB) * HH + j0 + c2], hn1);
            out[((size_t)t * BB + b0 + bA) * HH + j0 + c2] = hn0;
            out[((size_t)t * BB + b0 + bB) * HH + j0 + c2] = hn1;
        }

        group_barrier(grp);   // h complete before next step
    }
}

// =====================================================================================
extern "C" void kernel_launch(void* const* d_in, const int* in_sizes, int n_in,
                              void* d_out, int out_size)
{
    const float* x  = (const float*)d_in[0];
    const float* h0 = (const float*)d_in[1];
    const float* Wz = (const float*)d_in[2];
    const float* bz = (const float*)d_in[3];
    const float* Wr = (const float*)d_in[4];
    const float* br = (const float*)d_in[5];
    const float* Wh = (const float*)d_in[6];
    const float* bh = (const float*)d_in[7];
    float* out = (float*)d_out;

    const int smem_bytes = (3 * HH * JC + HH * HPAD + 2 * GB * JC) * (int)sizeof(float);
    cudaFuncSetAttribute(phase2_gru, cudaFuncAttributeMaxDynamicSharedMemorySize, smem_bytes);

    dim3 g1((TT * BB) / 128, 24);
    phase1_gemm<<<g1, 256>>>(x, Wz, bz, Wr, br, Wh, bh);

    phase2_gru<<<NGROUPS * GC, NT, smem_bytes>>>(h0, Wz, Wr, Wh, out);
}